// round 13
// baseline (speedup 1.0000x reference)
#include <cuda_runtime.h>
#include <cuda_fp16.h>

#define WIN   3072
#define HOP   192
#define NB    8
#define NT    1000
#define NF    128
#define NOISE_LEN ((NT-1)*HOP)   /* 191808 */
#define HALF  (WIN/2)            /* 1536 */
#define NTHREADS 256

#define PHY(i) ((i) + ((i)>>5))
#define SBUF (WIN + (WIN>>5))    /* 3168 */
#define SMEM_BYTES (2*SBUF*(int)sizeof(float2))   /* 50688 */

__device__ float2 g_tw[WIN];      // w3072^j = exp(-2*pi*i*j/3072)
__device__ float  g_hann[WIN];
__device__ __half g_scratch[NB*NT*WIN];   // windowed out_frames, fp16, ~49 MB

// ---------------------------------------------------------------- scalar ops
// a + b as FFMA with immediate multiplier 1.0 (rt_SMSP=1 vs FADD's 2).
__device__ __forceinline__ float fadd1(float a, float b){
    float r; asm("fma.rn.f32 %0, %1, 0f3F800000, %2;" : "=f"(r) : "f"(a), "f"(b)); return r;
}
// a - b == b*(-1.0) + a, same imm-FFMA form. Bit-exact.
__device__ __forceinline__ float fsub1(float a, float b){
    float r; asm("fma.rn.f32 %0, %1, 0fBF800000, %2;" : "=f"(r) : "f"(b), "f"(a)); return r;
}

// ---------------------------------------------------------------- complex ops
__device__ __forceinline__ float2 cadd(float2 a, float2 b){
    return make_float2(fadd1(a.x,b.x), fadd1(a.y,b.y));
}
__device__ __forceinline__ float2 csub(float2 a, float2 b){
    return make_float2(fsub1(a.x,b.x), fsub1(a.y,b.y));
}
__device__ __forceinline__ float2 cmul(float2 a, float2 b){
    return make_float2(a.x*b.x - a.y*b.y, a.x*b.y + a.y*b.x);
}

// forward DFT-4 (e^{-2pi i jk/4})
__device__ __forceinline__ void dft4(float2 &a0, float2 &a1, float2 &a2, float2 &a3){
    float2 t0 = cadd(a0,a2), t1 = csub(a0,a2);
    float2 t2 = cadd(a1,a3), t3 = csub(a1,a3);
    a0 = cadd(t0,t2);
    a2 = csub(t0,t2);
    a1 = make_float2(fadd1(t1.x, t3.y), fsub1(t1.y, t3.x));  // t1 - i*t3
    a3 = make_float2(fsub1(t1.x, t3.y), fadd1(t1.y, t3.x));  // t1 + i*t3
}

// forward DFT-3; H3/0.5 multiplies folded into imm-FFMAs
__device__ __forceinline__ void dft3(float2 &a, float2 &b, float2 &c){
    const float H3 = 0.8660254037844386f;
    float2 s = cadd(b,c);
    float2 d = csub(b,c);
    float tx = __fmaf_rn(s.x, -0.5f, a.x);
    float ty = __fmaf_rn(s.y, -0.5f, a.y);
    float2 y0 = cadd(a,s);
    b = make_float2(__fmaf_rn(d.y,  H3, tx), __fmaf_rn(d.x, -H3, ty));  // t - i*u
    c = make_float2(__fmaf_rn(d.y, -H3, tx), __fmaf_rn(d.x,  H3, ty));  // t + i*u
    a = y0;
}

// DFT-12, input v[j] with j = r + 4c. After: X[k3 + 3*k1] at v[k1 + 4*k3].
__device__ __forceinline__ void dft12(float2 *v){
    dft3(v[0], v[4], v[8]);
    dft3(v[1], v[5], v[9]);
    dft3(v[2], v[6], v[10]);
    dft3(v[3], v[7], v[11]);
    const float H3 = 0.8660254037844386f;
    v[5]  = cmul(v[5],  make_float2( H3,  -0.5f));   // w12^1
    v[6]  = cmul(v[6],  make_float2( 0.5f, -H3));    // w12^2
    v[7]  = make_float2(v[7].y, -v[7].x);            // w12^3 = -i
    v[9]  = cmul(v[9],  make_float2( 0.5f, -H3));    // w12^2
    v[10] = cmul(v[10], make_float2(-0.5f, -H3));    // w12^4
    v[11] = make_float2(-v[11].x, -v[11].y);         // w12^6 = -1
    dft4(v[0], v[1], v[2],  v[3]);
    dft4(v[4], v[5], v[6],  v[7]);
    dft4(v[8], v[9], v[10], v[11]);
}

// DFT-16, input v[j] with j = r + 4c. After: X[k4 + 4*k1] at v[k1 + 4*k4].
__device__ __forceinline__ void dft16(float2 *v){
    dft4(v[0], v[4], v[8],  v[12]);
    dft4(v[1], v[5], v[9],  v[13]);
    dft4(v[2], v[6], v[10], v[14]);
    dft4(v[3], v[7], v[11], v[15]);
    const float C1 = 0.9238795325112867f;
    const float S1 = 0.3826834323650898f;
    const float R2 = 0.7071067811865476f;
    v[5]  = cmul(v[5],  make_float2( C1, -S1));   // w16^1
    v[6]  = cmul(v[6],  make_float2( R2, -R2));   // w16^2
    v[7]  = cmul(v[7],  make_float2( S1, -C1));   // w16^3
    v[9]  = cmul(v[9],  make_float2( R2, -R2));   // w16^2
    v[10] = make_float2(v[10].y, -v[10].x);       // w16^4 = -i
    v[11] = cmul(v[11], make_float2(-R2, -R2));   // w16^6
    v[13] = cmul(v[13], make_float2( S1, -C1));   // w16^3
    v[14] = cmul(v[14], make_float2(-R2, -R2));   // w16^6
    v[15] = cmul(v[15], make_float2(-C1,  S1));   // w16^9
    dft4(v[0], v[1], v[2],  v[3]);
    dft4(v[4], v[5], v[6],  v[7]);
    dft4(v[8], v[9], v[10], v[11]);
    dft4(v[12],v[13],v[14], v[15]);
}

// radix-16 MIDDLE stage: src -> dst, 192 butterflies (tid = 12*p + q), twiddled
__device__ __forceinline__ void stage16_mid(const float2 *src, float2 *dst, int tid){
    if (tid < 192){
        float2 v[16];
        int q = tid % 12, p = tid / 12;
        #pragma unroll
        for (int i = 0; i < 16; i++) v[i] = src[PHY(tid + 192*i)];
        dft16(v);
        #pragma unroll
        for (int k = 0; k < 16; k++){
            float2 X = v[(k>>2) + 4*(k&3)];
            if (k && p) X = cmul(X, g_tw[12*p*k]);   // w256^{pk}
            dst[PHY(q + 192*p + 12*k)] = X;
        }
    }
    __syncthreads();
}

// radix-16 LAST stage: src -> dst, NO twiddle, output mapping tid + 192*k
__device__ __forceinline__ void stage16_last(const float2 *src, float2 *dst, int tid){
    if (tid < 192){
        float2 v[16];
        #pragma unroll
        for (int i = 0; i < 16; i++) v[i] = src[PHY(tid + 192*i)];
        dft16(v);
        #pragma unroll
        for (int k = 0; k < 16; k++){
            float2 X = v[(k>>2) + 4*(k&3)];
            dst[PHY(tid + 192*k)] = X;
        }
    }
    __syncthreads();
}

// ---------------------------------------------------------------- kernels
__global__ void init_tables(){
    int j = blockIdx.x*blockDim.x + threadIdx.x;
    if (j < WIN){
        float s, c;
        sincospif(-2.0f * (float)j / (float)WIN, &s, &c);
        g_tw[j] = make_float2(c, s);
        float sh = sinpif((float)j / (float)(WIN-1));
        g_hann[j] = sh * sh;   // 0.5 - 0.5*cos(2*pi*j/(N-1))
    }
}

// One block = one PAIR of frames (2t, 2t+1) packed as z = x + i*y.
// Fully fused: gmem->stage1, filter->stage1', stage3'->gmem(fp16). 6 barriers.
__global__ void __launch_bounds__(NTHREADS, 3)
synth_kernel(const float* __restrict__ fb, const float* __restrict__ noise){
    extern __shared__ float2 smem2[];
    float2* Za = smem2;          // buffer A
    float2* Zb = smem2 + SBUF;   // buffer B
    __shared__ float gsx[NF];
    __shared__ float gsy[NF];

    int tp  = blockIdx.x;          // 0..499
    int b   = blockIdx.y;
    int tid = threadIdx.x;
    int t0  = 2*tp;

    // filter gains for frames t0, t0+1 (consumed after >=3 barriers: safe)
    if (tid < NF){
        float2 g2 = *(const float2*)&fb[(b*NF + tid)*NT + t0];
        gsx[tid] = g2.x;
        gsy[tid] = g2.y;
    }

    int base = t0*HOP - HALF;
    const float* nb = noise + b*NOISE_LEN;

    // ======== forward FFT: gmem -> s1 -> Zb -> s2(mid) -> Za -> s3(last) -> Zb
    {
        float2 v[12];
        int p = tid;
        #pragma unroll
        for (int i = 0; i < 12; i++){
            int n  = p + 256*i;
            int i0 = base + n;
            int i1 = i0 + HOP;
            float x = (i0 >= 0 && i0 < NOISE_LEN) ? __ldg(&nb[i0]) : 0.0f;
            float y = (i1 >= 0 && i1 < NOISE_LEN) ? __ldg(&nb[i1]) : 0.0f;
            v[i] = make_float2(x, y);
        }
        dft12(v);
        #pragma unroll
        for (int k = 0; k < 12; k++){
            float2 X = v[(k/3) + 4*(k%3)];
            if (k) X = cmul(X, g_tw[p*k]);
            Zb[PHY(12*p + k)] = X;
        }
        __syncthreads();
    }
    stage16_mid (Zb, Za, tid);   // s2 (twiddled)
    stage16_last(Za, Zb, tid);   // s3 (no twiddle): forward spectrum now in Zb

    // ======== inverse FFT with fused filter:
    //   s1' reads filtered spectrum directly from Zb, writes Za
    {
        float2 v[12];
        int p = tid;
        #pragma unroll
        for (int i = 0; i < 12; i++){
            int n = p + 256*i;
            float2 W;
            if (n == 0){
                W = make_float2(0.0f, 0.0f);                 // H[0] = 0
            } else if (n == HALF){
                float2 A = Zb[PHY(HALF)];                    // Nyquist (X,Y real)
                W = make_float2(gsx[NF-1]*A.x, -gsy[NF-1]*A.y);
            } else {
                int k    = (n < HALF) ? n : (WIN - n);       // 1..1535
                float2 A = Zb[PHY(k)];
                float2 B = Zb[PHY(WIN - k)];
                float Xx = 0.5f*(A.x + B.x), Xy = 0.5f*(A.y - B.y);
                float Yx = 0.5f*(A.y + B.y), Yy = -0.5f*(A.x - B.x);
                int band = (k - 1)/12;
                float hx = gsx[band], hy = gsy[band];
                if (n < HALF){
                    W = make_float2(hx*Xx - hy*Yy, -(hx*Xy + hy*Yx));
                } else {
                    W = make_float2(hx*Xx + hy*Yy, -(-hx*Xy + hy*Yx));
                }
            }
            v[i] = W;
        }
        dft12(v);
        #pragma unroll
        for (int k = 0; k < 12; k++){
            float2 X = v[(k/3) + 4*(k%3)];
            if (k) X = cmul(X, g_tw[p*k]);
            Za[PHY(12*p + k)] = X;
        }
        __syncthreads();
    }
    stage16_mid(Za, Zb, tid);   // s2' (twiddled)

    // s3' (last): Zb -> registers -> windowed, coalesced fp16 STG to scratch
    if (tid < 192){
        float2 v[16];
        #pragma unroll
        for (int i = 0; i < 16; i++) v[i] = Zb[PHY(tid + 192*i)];
        dft16(v);
        const float inv = 1.0f/(float)WIN;
        __half* scx = g_scratch + (size_t)(b*NT + t0)*WIN;
        __half* scy = scx + WIN;
        #pragma unroll
        for (int k = 0; k < 16; k++){
            float2 X = v[(k>>2) + 4*(k&3)];
            int n = tid + 192*k;
            float w = inv * __ldg(&g_hann[n]);
            scx[n] = __float2half_rn( X.x * w);   // frame t0
            scy[n] = __float2half_rn(-X.y * w);   // frame t0+1
        }
    }
}

// 4 consecutive outputs per thread; interior frames contribute one aligned
// 8-byte load (4 halfs).
__global__ void ola_kernel(float* __restrict__ out){
    const int GP = NOISE_LEN/4;            // 47952 groups per batch
    int gid = blockIdx.x*blockDim.x + threadIdx.x;
    if (gid >= NB*GP) return;
    int b = gid / GP;
    int g = gid - b*GP;
    int s = 4*g + HALF;                    // s % 4 == 0
    const __half* base = g_scratch + (size_t)b*NT*WIN;

    int tl0 = (s     >= 2880) ? (s     - 2880)/HOP : 0;   // t_lo for element 0
    int tl3 = (s + 3 >= 2880) ? (s + 3 - 2880)/HOP : 0;   // t_lo for element 3
    int th0 = s/HOP;       if (th0 > NT-1) th0 = NT-1;    // t_hi for element 0
    int th3 = (s + 3)/HOP; if (th3 > NT-1) th3 = NT-1;    // t_hi for element 3

    float4 acc = make_float4(0.f, 0.f, 0.f, 0.f);
    // frames valid for all 4 elements: one 8-byte load (offset is mult of 4 halfs)
    for (int tt = tl3; tt <= th0; tt++){
        const __half2* p2 = (const __half2*)&base[tt*WIN + (s - HOP*tt)];
        float2 lo = __half22float2(p2[0]);
        float2 hi = __half22float2(p2[1]);
        acc.x += lo.x; acc.y += lo.y; acc.z += hi.x; acc.w += hi.y;
    }
    for (int tt = tl0; tt < tl3; tt++){
        int o0 = s - HOP*tt;
        if (o0+0 <= WIN-1) acc.x += __half2float(base[tt*WIN + o0+0]);
        if (o0+1 <= WIN-1) acc.y += __half2float(base[tt*WIN + o0+1]);
        if (o0+2 <= WIN-1) acc.z += __half2float(base[tt*WIN + o0+2]);
        if (o0+3 <= WIN-1) acc.w += __half2float(base[tt*WIN + o0+3]);
    }
    for (int tt = th0+1; tt <= th3; tt++){
        int o0 = s - HOP*tt;
        if (o0+0 >= 0) acc.x += __half2float(base[tt*WIN + o0+0]);
        if (o0+1 >= 0) acc.y += __half2float(base[tt*WIN + o0+1]);
        if (o0+2 >= 0) acc.z += __half2float(base[tt*WIN + o0+2]);
        if (o0+3 >= 0) acc.w += __half2float(base[tt*WIN + o0+3]);
    }
    *(float4*)&out[b*NOISE_LEN + 4*g] = acc;
}

// ---------------------------------------------------------------- launch
extern "C" void kernel_launch(void* const* d_in, const int* in_sizes, int n_in,
                              void* d_out, int out_size){
    const float* fb    = (const float*)d_in[0];
    const float* noise = (const float*)d_in[1];
    if (n_in >= 2 && in_sizes[0] == NB*NOISE_LEN && in_sizes[1] == NB*NF*NT){
        const float* tmp = fb; fb = noise; noise = tmp;
    }
    float* out = (float*)d_out;

    cudaFuncSetAttribute(synth_kernel,
                         cudaFuncAttributeMaxDynamicSharedMemorySize, SMEM_BYTES);

    init_tables<<<(WIN + 255)/256, 256>>>();
    dim3 grid(NT/2, NB);
    synth_kernel<<<grid, NTHREADS, SMEM_BYTES>>>(fb, noise);
    int n_groups = NB*(NOISE_LEN/4);
    ola_kernel<<<(n_groups + 255)/256, 256>>>(out);
}

// round 14
// speedup vs baseline: 1.0680x; 1.0680x over previous
#include <cuda_runtime.h>
#include <cuda_fp16.h>

#define WIN   3072
#define HOP   192
#define NB    8
#define NT    1000
#define NPAIR (NT/2)             /* 500 */
#define NF    128
#define NOISE_LEN ((NT-1)*HOP)   /* 191808 */
#define HALF  (WIN/2)            /* 1536 */
#define PLEN  (WIN + HOP)        /* 3264: merged pair-frame span */
#define NTHREADS 256

#define PHY(i) ((i) + ((i)>>5))
#define SBUF (WIN + (WIN>>5))    /* 3168 */
#define SMEM_BYTES (2*SBUF*(int)sizeof(float2))   /* 50688 */

__device__ float2 g_tw[WIN];      // w3072^j = exp(-2*pi*i*j/3072)
__device__ float  g_hann[WIN];
__device__ __half g_scratch[NB*NPAIR*PLEN];   // merged windowed pair-frames, ~26 MB

// ---------------------------------------------------------------- complex ops
__device__ __forceinline__ float2 cadd(float2 a, float2 b){ return make_float2(a.x+b.x, a.y+b.y); }
__device__ __forceinline__ float2 csub(float2 a, float2 b){ return make_float2(a.x-b.x, a.y-b.y); }
__device__ __forceinline__ float2 cmul(float2 a, float2 b){
    return make_float2(a.x*b.x - a.y*b.y, a.x*b.y + a.y*b.x);
}

// forward DFT-4 (e^{-2pi i jk/4})
__device__ __forceinline__ void dft4(float2 &a0, float2 &a1, float2 &a2, float2 &a3){
    float2 t0 = cadd(a0,a2), t1 = csub(a0,a2);
    float2 t2 = cadd(a1,a3), t3 = csub(a1,a3);
    a0 = cadd(t0,t2);
    a2 = csub(t0,t2);
    a1 = make_float2(t1.x + t3.y, t1.y - t3.x);  // t1 - i*t3
    a3 = make_float2(t1.x - t3.y, t1.y + t3.x);  // t1 + i*t3
}

// forward DFT-3
__device__ __forceinline__ void dft3(float2 &a, float2 &b, float2 &c){
    float2 s = cadd(b,c);
    float2 d = csub(b,c);
    float2 t = make_float2(a.x - 0.5f*s.x, a.y - 0.5f*s.y);
    float ux = 0.8660254037844386f*d.x, uy = 0.8660254037844386f*d.y;
    float2 y0 = cadd(a,s);
    b = make_float2(t.x + uy, t.y - ux);  // t - i*u
    c = make_float2(t.x - uy, t.y + ux);  // t + i*u
    a = y0;
}

// DFT-12, input v[j] with j = r + 4c. After: X[k3 + 3*k1] at v[k1 + 4*k3].
__device__ __forceinline__ void dft12(float2 *v){
    dft3(v[0], v[4], v[8]);
    dft3(v[1], v[5], v[9]);
    dft3(v[2], v[6], v[10]);
    dft3(v[3], v[7], v[11]);
    const float H3 = 0.8660254037844386f;
    v[5]  = cmul(v[5],  make_float2( H3,  -0.5f));   // w12^1
    v[6]  = cmul(v[6],  make_float2( 0.5f, -H3));    // w12^2
    v[7]  = make_float2(v[7].y, -v[7].x);            // w12^3 = -i
    v[9]  = cmul(v[9],  make_float2( 0.5f, -H3));    // w12^2
    v[10] = cmul(v[10], make_float2(-0.5f, -H3));    // w12^4
    v[11] = make_float2(-v[11].x, -v[11].y);         // w12^6 = -1
    dft4(v[0], v[1], v[2],  v[3]);
    dft4(v[4], v[5], v[6],  v[7]);
    dft4(v[8], v[9], v[10], v[11]);
}

// DFT-16, input v[j] with j = r + 4c. After: X[k4 + 4*k1] at v[k1 + 4*k4].
__device__ __forceinline__ void dft16(float2 *v){
    dft4(v[0], v[4], v[8],  v[12]);
    dft4(v[1], v[5], v[9],  v[13]);
    dft4(v[2], v[6], v[10], v[14]);
    dft4(v[3], v[7], v[11], v[15]);
    const float C1 = 0.9238795325112867f;
    const float S1 = 0.3826834323650898f;
    const float R2 = 0.7071067811865476f;
    v[5]  = cmul(v[5],  make_float2( C1, -S1));   // w16^1
    v[6]  = cmul(v[6],  make_float2( R2, -R2));   // w16^2
    v[7]  = cmul(v[7],  make_float2( S1, -C1));   // w16^3
    v[9]  = cmul(v[9],  make_float2( R2, -R2));   // w16^2
    v[10] = make_float2(v[10].y, -v[10].x);       // w16^4 = -i
    v[11] = cmul(v[11], make_float2(-R2, -R2));   // w16^6
    v[13] = cmul(v[13], make_float2( S1, -C1));   // w16^3
    v[14] = cmul(v[14], make_float2(-R2, -R2));   // w16^6
    v[15] = cmul(v[15], make_float2(-C1,  S1));   // w16^9
    dft4(v[0], v[1], v[2],  v[3]);
    dft4(v[4], v[5], v[6],  v[7]);
    dft4(v[8], v[9], v[10], v[11]);
    dft4(v[12],v[13],v[14], v[15]);
}

// radix-16 MIDDLE stage: src -> dst, 192 butterflies (tid = 12*p + q), twiddled
__device__ __forceinline__ void stage16_mid(const float2 *src, float2 *dst, int tid){
    if (tid < 192){
        float2 v[16];
        int q = tid % 12, p = tid / 12;
        #pragma unroll
        for (int i = 0; i < 16; i++) v[i] = src[PHY(tid + 192*i)];
        dft16(v);
        #pragma unroll
        for (int k = 0; k < 16; k++){
            float2 X = v[(k>>2) + 4*(k&3)];
            if (k && p) X = cmul(X, g_tw[12*p*k]);   // w256^{pk}
            dst[PHY(q + 192*p + 12*k)] = X;
        }
    }
    __syncthreads();
}

// radix-16 LAST stage: src -> dst, NO twiddle, output mapping tid + 192*k
__device__ __forceinline__ void stage16_last(const float2 *src, float2 *dst, int tid){
    if (tid < 192){
        float2 v[16];
        #pragma unroll
        for (int i = 0; i < 16; i++) v[i] = src[PHY(tid + 192*i)];
        dft16(v);
        #pragma unroll
        for (int k = 0; k < 16; k++){
            float2 X = v[(k>>2) + 4*(k&3)];
            dst[PHY(tid + 192*k)] = X;
        }
    }
    __syncthreads();
}

// ---------------------------------------------------------------- kernels
__global__ void init_tables(){
    int j = blockIdx.x*blockDim.x + threadIdx.x;
    if (j < WIN){
        float s, c;
        sincospif(-2.0f * (float)j / (float)WIN, &s, &c);
        g_tw[j] = make_float2(c, s);
        float sh = sinpif((float)j / (float)(WIN-1));
        g_hann[j] = sh * sh;   // 0.5 - 0.5*cos(2*pi*j/(N-1))
    }
}

// One block = one PAIR of frames (2u, 2u+1) packed as z = x + i*y.
// Fully fused: gmem->stage1, filter->stage1', stage3'->merged-OLA-pair->gmem.
__global__ void __launch_bounds__(NTHREADS, 3)
synth_kernel(const float* __restrict__ fb, const float* __restrict__ noise){
    extern __shared__ float2 smem2[];
    float2* Za = smem2;          // buffer A
    float2* Zb = smem2 + SBUF;   // buffer B
    __shared__ float gsx[NF];
    __shared__ float gsy[NF];

    int tp  = blockIdx.x;          // pair index u: 0..499
    int b   = blockIdx.y;
    int tid = threadIdx.x;
    int t0  = 2*tp;

    // filter gains for frames t0, t0+1 (consumed after >=3 barriers: safe)
    if (tid < NF){
        float2 g2 = *(const float2*)&fb[(b*NF + tid)*NT + t0];
        gsx[tid] = g2.x;
        gsy[tid] = g2.y;
    }

    int base = t0*HOP - HALF;
    const float* nb = noise + b*NOISE_LEN;

    // ======== forward FFT: gmem -> s1 -> Zb -> s2(mid) -> Za -> s3(last) -> Zb
    {
        float2 v[12];
        int p = tid;
        #pragma unroll
        for (int i = 0; i < 12; i++){
            int n  = p + 256*i;
            int i0 = base + n;
            int i1 = i0 + HOP;
            float x = (i0 >= 0 && i0 < NOISE_LEN) ? __ldg(&nb[i0]) : 0.0f;
            float y = (i1 >= 0 && i1 < NOISE_LEN) ? __ldg(&nb[i1]) : 0.0f;
            v[i] = make_float2(x, y);
        }
        dft12(v);
        #pragma unroll
        for (int k = 0; k < 12; k++){
            float2 X = v[(k/3) + 4*(k%3)];
            if (k) X = cmul(X, g_tw[p*k]);
            Zb[PHY(12*p + k)] = X;
        }
        __syncthreads();
    }
    stage16_mid (Zb, Za, tid);   // s2 (twiddled)
    stage16_last(Za, Zb, tid);   // s3 (no twiddle): forward spectrum now in Zb

    // ======== inverse FFT with fused filter:
    //   s1' reads filtered spectrum directly from Zb, writes Za
    {
        float2 v[12];
        int p = tid;
        #pragma unroll
        for (int i = 0; i < 12; i++){
            int n = p + 256*i;
            float2 W;
            if (n == 0){
                W = make_float2(0.0f, 0.0f);                 // H[0] = 0
            } else if (n == HALF){
                float2 A = Zb[PHY(HALF)];                    // Nyquist (X,Y real)
                W = make_float2(gsx[NF-1]*A.x, -gsy[NF-1]*A.y);
            } else {
                int k    = (n < HALF) ? n : (WIN - n);       // 1..1535
                float2 A = Zb[PHY(k)];
                float2 B = Zb[PHY(WIN - k)];
                float Xx = 0.5f*(A.x + B.x), Xy = 0.5f*(A.y - B.y);
                float Yx = 0.5f*(A.y + B.y), Yy = -0.5f*(A.x - B.x);
                int band = (k - 1)/12;
                float hx = gsx[band], hy = gsy[band];
                if (n < HALF){
                    W = make_float2(hx*Xx - hy*Yy, -(hx*Xy + hy*Yx));
                } else {
                    W = make_float2(hx*Xx + hy*Yy, -(-hx*Xy + hy*Yx));
                }
            }
            v[i] = W;
        }
        dft12(v);
        #pragma unroll
        for (int k = 0; k < 12; k++){
            float2 X = v[(k/3) + 4*(k%3)];
            if (k) X = cmul(X, g_tw[p*k]);
            Za[PHY(12*p + k)] = X;
        }
        __syncthreads();
    }
    stage16_mid(Za, Zb, tid);   // s2' (twiddled)

    // s3' (last, no twiddle): Zb -> registers -> merged pair-OLA -> fp16 gmem.
    // Thread tid holds both frames at n = tid + 192k:
    //   f0[n] =  Re/N, f1[n] = -Im/N.
    // Merged pair buffer: P[m] = w[m]*f0[m] + w[m-192]*f1[m-192], m in [0,3264).
    // P[tid+192j] uses X_j (f0 term) and X_{j-1} (f1 term): register-local.
    if (tid < 192){
        float2 v[16];
        #pragma unroll
        for (int i = 0; i < 16; i++) v[i] = Zb[PHY(tid + 192*i)];
        dft16(v);
        const float inv = 1.0f/(float)WIN;
        __half* sc = g_scratch + (size_t)(b*NPAIR + tp)*PLEN;
        float prev = 0.0f;   // f1[n(j-1)] * w[n(j-1)]
        #pragma unroll
        for (int j = 0; j < 16; j++){
            float2 X = v[(j>>2) + 4*(j&3)];
            float wj = inv * __ldg(&g_hann[tid + 192*j]);
            sc[tid + 192*j] = __float2half_rn(X.x*wj + prev);
            prev = -X.y*wj;
        }
        sc[tid + 192*16] = __float2half_rn(prev);   // m in [3072, 3264): f1 only
    }
}

// 4 consecutive outputs per thread. Pair-frames span 3264 with stride 384.
// s % 4 == 0 and offsets o = s - 384u are multiples of 4 with o <= 3260,
// so ALL u in [u_lo, u_hi] are valid for all 4 elements: no edge handling.
__global__ void ola_kernel(float* __restrict__ out){
    const int GP = NOISE_LEN/4;            // 47952 groups per batch
    int gid = blockIdx.x*blockDim.x + threadIdx.x;
    if (gid >= NB*GP) return;
    int b = gid / GP;
    int g = gid - b*GP;
    int s = 4*g + HALF;                    // padded-timeline position, s % 4 == 0
    const __half* base = g_scratch + (size_t)b*NPAIR*PLEN;

    int u_hi = s/384;                  if (u_hi > NPAIR-1) u_hi = NPAIR-1;
    int u_lo = (s >= PLEN) ? (s - PLEN)/384 + 1 : 0;

    float4 acc = make_float4(0.f, 0.f, 0.f, 0.f);
    for (int u = u_lo; u <= u_hi; u++){
        const __half2* p2 = (const __half2*)&base[(size_t)u*PLEN + (s - 384*u)];
        float2 lo = __half22float2(p2[0]);
        float2 hi = __half22float2(p2[1]);
        acc.x += lo.x; acc.y += lo.y; acc.z += hi.x; acc.w += hi.y;
    }
    *(float4*)&out[b*NOISE_LEN + 4*g] = acc;
}

// ---------------------------------------------------------------- launch
extern "C" void kernel_launch(void* const* d_in, const int* in_sizes, int n_in,
                              void* d_out, int out_size){
    const float* fb    = (const float*)d_in[0];
    const float* noise = (const float*)d_in[1];
    if (n_in >= 2 && in_sizes[0] == NB*NOISE_LEN && in_sizes[1] == NB*NF*NT){
        const float* tmp = fb; fb = noise; noise = tmp;
    }
    float* out = (float*)d_out;

    cudaFuncSetAttribute(synth_kernel,
                         cudaFuncAttributeMaxDynamicSharedMemorySize, SMEM_BYTES);

    init_tables<<<(WIN + 255)/256, 256>>>();
    dim3 grid(NPAIR, NB);
    synth_kernel<<<grid, NTHREADS, SMEM_BYTES>>>(fb, noise);
    int n_groups = NB*(NOISE_LEN/4);
    ola_kernel<<<(n_groups + 255)/256, 256>>>(out);
}

// round 16
// speedup vs baseline: 1.2037x; 1.1270x over previous
#include <cuda_runtime.h>
#include <cuda_fp16.h>

#define WIN   3072
#define HOP   192
#define NB    8
#define NT    1000
#define NPAIR (NT/2)             /* 500 */
#define NF    128
#define NOISE_LEN ((NT-1)*HOP)   /* 191808 */
#define HALF  (WIN/2)            /* 1536 */
#define PLEN  (WIN + HOP)        /* 3264: merged pair-frame span */
#define NTHREADS 256

#define PHY(i) ((i) + ((i)>>5))
#define SBUF (WIN + (WIN>>5))    /* 3168 */
#define SMEM_BYTES (2*SBUF*(int)sizeof(float2))   /* 50688 */

__device__ float2 g_tw1[256];    // w3072^p, p in [0,256)           (2 KB)
__device__ float2 g_tw2[256];    // w256^{p*k} at [16p + k]         (2 KB)
__device__ float  g_hann[WIN];   //                                 (12 KB)
__device__ __half g_scratch[NB*NPAIR*PLEN];   // merged windowed pair-frames, ~26 MB

// ---------------------------------------------------------------- complex ops
__device__ __forceinline__ float2 cadd(float2 a, float2 b){ return make_float2(a.x+b.x, a.y+b.y); }
__device__ __forceinline__ float2 csub(float2 a, float2 b){ return make_float2(a.x-b.x, a.y-b.y); }
__device__ __forceinline__ float2 cmul(float2 a, float2 b){
    return make_float2(a.x*b.x - a.y*b.y, a.x*b.y + a.y*b.x);
}

// forward DFT-4 (e^{-2pi i jk/4})
__device__ __forceinline__ void dft4(float2 &a0, float2 &a1, float2 &a2, float2 &a3){
    float2 t0 = cadd(a0,a2), t1 = csub(a0,a2);
    float2 t2 = cadd(a1,a3), t3 = csub(a1,a3);
    a0 = cadd(t0,t2);
    a2 = csub(t0,t2);
    a1 = make_float2(t1.x + t3.y, t1.y - t3.x);  // t1 - i*t3
    a3 = make_float2(t1.x - t3.y, t1.y + t3.x);  // t1 + i*t3
}

// forward DFT-3
__device__ __forceinline__ void dft3(float2 &a, float2 &b, float2 &c){
    float2 s = cadd(b,c);
    float2 d = csub(b,c);
    float2 t = make_float2(a.x - 0.5f*s.x, a.y - 0.5f*s.y);
    float ux = 0.8660254037844386f*d.x, uy = 0.8660254037844386f*d.y;
    float2 y0 = cadd(a,s);
    b = make_float2(t.x + uy, t.y - ux);  // t - i*u
    c = make_float2(t.x - uy, t.y + ux);  // t + i*u
    a = y0;
}

// DFT-12, input v[j] with j = r + 4c. After: X[k3 + 3*k1] at v[k1 + 4*k3].
__device__ __forceinline__ void dft12(float2 *v){
    dft3(v[0], v[4], v[8]);
    dft3(v[1], v[5], v[9]);
    dft3(v[2], v[6], v[10]);
    dft3(v[3], v[7], v[11]);
    const float H3 = 0.8660254037844386f;
    v[5]  = cmul(v[5],  make_float2( H3,  -0.5f));   // w12^1
    v[6]  = cmul(v[6],  make_float2( 0.5f, -H3));    // w12^2
    v[7]  = make_float2(v[7].y, -v[7].x);            // w12^3 = -i
    v[9]  = cmul(v[9],  make_float2( 0.5f, -H3));    // w12^2
    v[10] = cmul(v[10], make_float2(-0.5f, -H3));    // w12^4
    v[11] = make_float2(-v[11].x, -v[11].y);         // w12^6 = -1
    dft4(v[0], v[1], v[2],  v[3]);
    dft4(v[4], v[5], v[6],  v[7]);
    dft4(v[8], v[9], v[10], v[11]);
}

// DFT-16, input v[j] with j = r + 4c. After: X[k4 + 4*k1] at v[k1 + 4*k4].
__device__ __forceinline__ void dft16(float2 *v){
    dft4(v[0], v[4], v[8],  v[12]);
    dft4(v[1], v[5], v[9],  v[13]);
    dft4(v[2], v[6], v[10], v[14]);
    dft4(v[3], v[7], v[11], v[15]);
    const float C1 = 0.9238795325112867f;
    const float S1 = 0.3826834323650898f;
    const float R2 = 0.7071067811865476f;
    v[5]  = cmul(v[5],  make_float2( C1, -S1));   // w16^1
    v[6]  = cmul(v[6],  make_float2( R2, -R2));   // w16^2
    v[7]  = cmul(v[7],  make_float2( S1, -C1));   // w16^3
    v[9]  = cmul(v[9],  make_float2( R2, -R2));   // w16^2
    v[10] = make_float2(v[10].y, -v[10].x);       // w16^4 = -i
    v[11] = cmul(v[11], make_float2(-R2, -R2));   // w16^6
    v[13] = cmul(v[13], make_float2( S1, -C1));   // w16^3
    v[14] = cmul(v[14], make_float2(-R2, -R2));   // w16^6
    v[15] = cmul(v[15], make_float2(-C1,  S1));   // w16^9
    dft4(v[0], v[1], v[2],  v[3]);
    dft4(v[4], v[5], v[6],  v[7]);
    dft4(v[8], v[9], v[10], v[11]);
    dft4(v[12],v[13],v[14], v[15]);
}

// radix-16 MIDDLE stage: src -> dst, 192 butterflies (tid = 12*p + q), twiddled
// from the compact 256-entry w256 table (2 KB, L1-resident at any occupancy).
__device__ __forceinline__ void stage16_mid(const float2 *src, float2 *dst, int tid){
    if (tid < 192){
        float2 v[16];
        int q = tid % 12, p = tid / 12;
        #pragma unroll
        for (int i = 0; i < 16; i++) v[i] = src[PHY(tid + 192*i)];
        dft16(v);
        #pragma unroll
        for (int k = 0; k < 16; k++){
            float2 X = v[(k>>2) + 4*(k&3)];
            if (k && p) X = cmul(X, g_tw2[(p<<4) + k]);   // w256^{pk}
            dst[PHY(q + 192*p + 12*k)] = X;
        }
    }
    __syncthreads();
}

// radix-16 LAST stage: src -> dst, NO twiddle, output mapping tid + 192*k
__device__ __forceinline__ void stage16_last(const float2 *src, float2 *dst, int tid){
    if (tid < 192){
        float2 v[16];
        #pragma unroll
        for (int i = 0; i < 16; i++) v[i] = src[PHY(tid + 192*i)];
        dft16(v);
        #pragma unroll
        for (int k = 0; k < 16; k++){
            float2 X = v[(k>>2) + 4*(k&3)];
            dst[PHY(tid + 192*k)] = X;
        }
    }
    __syncthreads();
}

// ---------------------------------------------------------------- kernels
__global__ void init_tables(){
    int j = blockIdx.x*blockDim.x + threadIdx.x;
    if (j < 256){
        float s, c;
        sincospif(-2.0f * (float)j / (float)WIN, &s, &c);
        g_tw1[j] = make_float2(c, s);
        int p = j >> 4, k = j & 15;
        float s2, c2;
        sincospif(-2.0f * (float)(p*k) / 256.0f, &s2, &c2);
        g_tw2[j] = make_float2(c2, s2);
    }
    if (j < WIN){
        float sh = sinpif((float)j / (float)(WIN-1));
        g_hann[j] = sh * sh;   // 0.5 - 0.5*cos(2*pi*j/(N-1))
    }
}

// One block = one PAIR of frames (2u, 2u+1) packed as z = x + i*y.
// Fully fused: gmem->stage1, filter->stage1', stage3'->merged-OLA-pair->gmem.
// Stage-1 twiddles chained from g_tw1[p] (w3072^p); tables total 4 KB so L1
// stays effective even at 4 blocks/SM (202 KB smem leaves ~26 KB L1).
__global__ void __launch_bounds__(NTHREADS, 4)
synth_kernel(const float* __restrict__ fb, const float* __restrict__ noise){
    extern __shared__ float2 smem2[];
    float2* Za = smem2;          // buffer A
    float2* Zb = smem2 + SBUF;   // buffer B
    __shared__ float gsx[NF];
    __shared__ float gsy[NF];

    int tp  = blockIdx.x;          // pair index u: 0..499
    int b   = blockIdx.y;
    int tid = threadIdx.x;
    int t0  = 2*tp;

    // filter gains for frames t0, t0+1 (consumed after >=3 barriers: safe)
    if (tid < NF){
        float2 g2 = *(const float2*)&fb[(b*NF + tid)*NT + t0];
        gsx[tid] = g2.x;
        gsy[tid] = g2.y;
    }

    int base = t0*HOP - HALF;
    const float* nb = noise + b*NOISE_LEN;

    // ======== forward FFT: gmem -> s1 -> Zb -> s2(mid) -> Za -> s3(last) -> Zb
    {
        float2 v[12];
        int p = tid;
        #pragma unroll
        for (int i = 0; i < 12; i++){
            int n  = p + 256*i;
            int i0 = base + n;
            int i1 = i0 + HOP;
            float x = (i0 >= 0 && i0 < NOISE_LEN) ? __ldg(&nb[i0]) : 0.0f;
            float y = (i1 >= 0 && i1 < NOISE_LEN) ? __ldg(&nb[i1]) : 0.0f;
            v[i] = make_float2(x, y);
        }
        float2 w1 = g_tw1[p];                    // w3072^p (coalesced, 2 KB table)
        dft12(v);
        Zb[PHY(12*p)] = v[0];
        float2 wc = w1;                          // wc = w3072^{p*k}
        #pragma unroll
        for (int k = 1; k < 12; k++){
            Zb[PHY(12*p + k)] = cmul(v[(k/3) + 4*(k%3)], wc);
            if (k < 11) wc = cmul(wc, w1);
        }
        __syncthreads();
    }
    stage16_mid (Zb, Za, tid);   // s2 (twiddled)
    stage16_last(Za, Zb, tid);   // s3 (no twiddle): forward spectrum now in Zb

    // ======== inverse FFT with fused filter:
    //   s1' reads filtered spectrum directly from Zb, writes Za
    {
        float2 v[12];
        int p = tid;
        #pragma unroll
        for (int i = 0; i < 12; i++){
            int n = p + 256*i;
            float2 W;
            if (n == 0){
                W = make_float2(0.0f, 0.0f);                 // H[0] = 0
            } else if (n == HALF){
                float2 A = Zb[PHY(HALF)];                    // Nyquist (X,Y real)
                W = make_float2(gsx[NF-1]*A.x, -gsy[NF-1]*A.y);
            } else {
                int k    = (n < HALF) ? n : (WIN - n);       // 1..1535
                float2 A = Zb[PHY(k)];
                float2 B = Zb[PHY(WIN - k)];
                float Xx = 0.5f*(A.x + B.x), Xy = 0.5f*(A.y - B.y);
                float Yx = 0.5f*(A.y + B.y), Yy = -0.5f*(A.x - B.x);
                int band = (k - 1)/12;
                float hx = gsx[band], hy = gsy[band];
                if (n < HALF){
                    W = make_float2(hx*Xx - hy*Yy, -(hx*Xy + hy*Yx));
                } else {
                    W = make_float2(hx*Xx + hy*Yy, -(-hx*Xy + hy*Yx));
                }
            }
            v[i] = W;
        }
        float2 w1 = g_tw1[p];
        dft12(v);
        Za[PHY(12*p)] = v[0];
        float2 wc = w1;
        #pragma unroll
        for (int k = 1; k < 12; k++){
            Za[PHY(12*p + k)] = cmul(v[(k/3) + 4*(k%3)], wc);
            if (k < 11) wc = cmul(wc, w1);
        }
        __syncthreads();
    }
    stage16_mid(Za, Zb, tid);   // s2' (twiddled)

    // s3' (last, no twiddle): Zb -> registers -> merged pair-OLA -> fp16 gmem.
    //   P[m] = w[m]*f0[m] + w[m-192]*f1[m-192], m in [0,3264); register-local.
    if (tid < 192){
        float2 v[16];
        #pragma unroll
        for (int i = 0; i < 16; i++) v[i] = Zb[PHY(tid + 192*i)];
        dft16(v);
        const float inv = 1.0f/(float)WIN;
        __half* sc = g_scratch + (size_t)(b*NPAIR + tp)*PLEN;
        float prev = 0.0f;   // f1[n(j-1)] * w[n(j-1)]
        #pragma unroll
        for (int j = 0; j < 16; j++){
            float2 X = v[(j>>2) + 4*(j&3)];
            float wj = inv * __ldg(&g_hann[tid + 192*j]);
            sc[tid + 192*j] = __float2half_rn(X.x*wj + prev);
            prev = -X.y*wj;
        }
        sc[tid + 192*16] = __float2half_rn(prev);   // m in [3072, 3264): f1 only
    }
}

// 8 consecutive outputs per thread. Pair-frames span 3264 with stride 384.
// s % 8 == 0 and o = s - 384u is a multiple of 8 with o <= 3256, so every
// u in [u_lo, u_hi] is valid for all 8 elements: edge-free 16-byte loads.
__global__ void ola_kernel(float* __restrict__ out){
    const int GP = NOISE_LEN/8;            // 23976 groups per batch
    int gid = blockIdx.x*blockDim.x + threadIdx.x;
    if (gid >= NB*GP) return;
    int b = gid / GP;
    int g = gid - b*GP;
    int s = 8*g + HALF;                    // padded-timeline position, s % 8 == 0
    const __half* base = g_scratch + (size_t)b*NPAIR*PLEN;

    int u_hi = s/384;                  if (u_hi > NPAIR-1) u_hi = NPAIR-1;
    int u_lo = (s >= PLEN) ? (s - PLEN)/384 + 1 : 0;

    float acc[8] = {0.f,0.f,0.f,0.f,0.f,0.f,0.f,0.f};
    for (int u = u_lo; u <= u_hi; u++){
        const uint4 raw = *(const uint4*)&base[(size_t)u*PLEN + (s - 384*u)];
        const __half2* h2 = (const __half2*)&raw;
        #pragma unroll
        for (int j = 0; j < 4; j++){
            float2 f = __half22float2(h2[j]);
            acc[2*j]   += f.x;
            acc[2*j+1] += f.y;
        }
    }
    float4* po = (float4*)&out[b*NOISE_LEN + 8*g];
    po[0] = make_float4(acc[0], acc[1], acc[2], acc[3]);
    po[1] = make_float4(acc[4], acc[5], acc[6], acc[7]);
}

// ---------------------------------------------------------------- launch
extern "C" void kernel_launch(void* const* d_in, const int* in_sizes, int n_in,
                              void* d_out, int out_size){
    const float* fb    = (const float*)d_in[0];
    const float* noise = (const float*)d_in[1];
    if (n_in >= 2 && in_sizes[0] == NB*NOISE_LEN && in_sizes[1] == NB*NF*NT){
        const float* tmp = fb; fb = noise; noise = tmp;
    }
    float* out = (float*)d_out;

    cudaFuncSetAttribute(synth_kernel,
                         cudaFuncAttributeMaxDynamicSharedMemorySize, SMEM_BYTES);

    init_tables<<<(WIN + 255)/256, 256>>>();
    dim3 grid(NPAIR, NB);
    synth_kernel<<<grid, NTHREADS, SMEM_BYTES>>>(fb, noise);
    int n_groups = NB*(NOISE_LEN/8);
    ola_kernel<<<(n_groups + 255)/256, 256>>>(out);
}

// round 17
// speedup vs baseline: 1.2350x; 1.0261x over previous
#include <cuda_runtime.h>
#include <cuda_fp16.h>

#define WIN   3072
#define HOP   192
#define NB    8
#define NT    1000
#define NPAIR (NT/2)             /* 500 */
#define NF    128
#define NOISE_LEN ((NT-1)*HOP)   /* 191808 */
#define HALF  (WIN/2)            /* 1536 */
#define PLEN  (WIN + HOP)        /* 3264: merged pair-frame span */
#define NTHREADS 256

#define PHY(i) ((i) + ((i)>>5))
#define SBUF (WIN + (WIN>>5))    /* 3168 */
#define SMEM_BYTES (2*SBUF*(int)sizeof(float2))   /* 50688 */

// ================================================================ compile-time tables
constexpr double K_PI = 3.141592653589793238462643383279502884;

// Taylor sin/cos, |x| <= pi, double precision (error ~1e-13 with 12 terms)
constexpr double tsin_(double x){
    double x2 = x*x, t = x, s = x;
    for (int n = 1; n <= 12; n++){ t *= -x2 / double((2*n)*(2*n+1)); s += t; }
    return s;
}
constexpr double tcos_(double x){
    double x2 = x*x, t = 1.0, s = 1.0;
    for (int n = 1; n <= 12; n++){ t *= -x2 / double((2*n-1)*(2*n)); s += t; }
    return s;
}

struct TwTbl  { float2 tw1[256]; float2 tw2[256]; };
struct HannTbl{ float  h[WIN]; };

constexpr TwTbl make_tw(){
    TwTbl r{};
    for (int p = 0; p < 256; p++){
        // w3072^p: theta in (-0.53, 0] — tiny, Taylor exact
        double th = -2.0*K_PI*(double)p/3072.0;
        r.tw1[p] = { (float)tcos_(th), (float)tsin_(th) };
    }
    for (int j = 0; j < 256; j++){
        int p = j >> 4, k = j & 15;
        int m = (p*k) & 255;                       // w256^{pk}, period 256
        double a = -2.0*K_PI*(double)m/256.0;
        if (m > 128) a += 2.0*K_PI;                // reduce to (-pi, pi]
        r.tw2[j] = { (float)tcos_(a), (float)tsin_(a) };
    }
    return r;
}
constexpr HannTbl make_hann(){
    HannTbl r{};
    for (int j = 0; j < WIN; j++){
        double x = K_PI*(double)j/(double)(WIN-1);     // [0, pi]
        if (x > K_PI*0.5) x = K_PI - x;                // sin(x) = sin(pi-x)
        double s = tsin_(x);
        r.h[j] = (float)(s*s);                         // 0.5 - 0.5*cos(2pi j/(N-1))
    }
    return r;
}

__device__ const TwTbl   g_twt  = make_tw();    // 4 KB, L1-resident
__device__ const HannTbl g_hant = make_hann();  // 12 KB
__device__ __half g_scratch[NB*NPAIR*PLEN];     // merged windowed pair-frames, ~26 MB

// ---------------------------------------------------------------- complex ops
__device__ __forceinline__ float2 cadd(float2 a, float2 b){ return make_float2(a.x+b.x, a.y+b.y); }
__device__ __forceinline__ float2 csub(float2 a, float2 b){ return make_float2(a.x-b.x, a.y-b.y); }
__device__ __forceinline__ float2 cmul(float2 a, float2 b){
    return make_float2(a.x*b.x - a.y*b.y, a.x*b.y + a.y*b.x);
}

// forward DFT-4 (e^{-2pi i jk/4})
__device__ __forceinline__ void dft4(float2 &a0, float2 &a1, float2 &a2, float2 &a3){
    float2 t0 = cadd(a0,a2), t1 = csub(a0,a2);
    float2 t2 = cadd(a1,a3), t3 = csub(a1,a3);
    a0 = cadd(t0,t2);
    a2 = csub(t0,t2);
    a1 = make_float2(t1.x + t3.y, t1.y - t3.x);  // t1 - i*t3
    a3 = make_float2(t1.x - t3.y, t1.y + t3.x);  // t1 + i*t3
}

// forward DFT-3
__device__ __forceinline__ void dft3(float2 &a, float2 &b, float2 &c){
    float2 s = cadd(b,c);
    float2 d = csub(b,c);
    float2 t = make_float2(a.x - 0.5f*s.x, a.y - 0.5f*s.y);
    float ux = 0.8660254037844386f*d.x, uy = 0.8660254037844386f*d.y;
    float2 y0 = cadd(a,s);
    b = make_float2(t.x + uy, t.y - ux);  // t - i*u
    c = make_float2(t.x - uy, t.y + ux);  // t + i*u
    a = y0;
}

// DFT-12, input v[j] with j = r + 4c. After: X[k3 + 3*k1] at v[k1 + 4*k3].
__device__ __forceinline__ void dft12(float2 *v){
    dft3(v[0], v[4], v[8]);
    dft3(v[1], v[5], v[9]);
    dft3(v[2], v[6], v[10]);
    dft3(v[3], v[7], v[11]);
    const float H3 = 0.8660254037844386f;
    v[5]  = cmul(v[5],  make_float2( H3,  -0.5f));   // w12^1
    v[6]  = cmul(v[6],  make_float2( 0.5f, -H3));    // w12^2
    v[7]  = make_float2(v[7].y, -v[7].x);            // w12^3 = -i
    v[9]  = cmul(v[9],  make_float2( 0.5f, -H3));    // w12^2
    v[10] = cmul(v[10], make_float2(-0.5f, -H3));    // w12^4
    v[11] = make_float2(-v[11].x, -v[11].y);         // w12^6 = -1
    dft4(v[0], v[1], v[2],  v[3]);
    dft4(v[4], v[5], v[6],  v[7]);
    dft4(v[8], v[9], v[10], v[11]);
}

// DFT-16, input v[j] with j = r + 4c. After: X[k4 + 4*k1] at v[k1 + 4*k4].
__device__ __forceinline__ void dft16(float2 *v){
    dft4(v[0], v[4], v[8],  v[12]);
    dft4(v[1], v[5], v[9],  v[13]);
    dft4(v[2], v[6], v[10], v[14]);
    dft4(v[3], v[7], v[11], v[15]);
    const float C1 = 0.9238795325112867f;
    const float S1 = 0.3826834323650898f;
    const float R2 = 0.7071067811865476f;
    v[5]  = cmul(v[5],  make_float2( C1, -S1));   // w16^1
    v[6]  = cmul(v[6],  make_float2( R2, -R2));   // w16^2
    v[7]  = cmul(v[7],  make_float2( S1, -C1));   // w16^3
    v[9]  = cmul(v[9],  make_float2( R2, -R2));   // w16^2
    v[10] = make_float2(v[10].y, -v[10].x);       // w16^4 = -i
    v[11] = cmul(v[11], make_float2(-R2, -R2));   // w16^6
    v[13] = cmul(v[13], make_float2( S1, -C1));   // w16^3
    v[14] = cmul(v[14], make_float2(-R2, -R2));   // w16^6
    v[15] = cmul(v[15], make_float2(-C1,  S1));   // w16^9
    dft4(v[0], v[1], v[2],  v[3]);
    dft4(v[4], v[5], v[6],  v[7]);
    dft4(v[8], v[9], v[10], v[11]);
    dft4(v[12],v[13],v[14], v[15]);
}

// radix-16 MIDDLE stage: src -> dst, 192 butterflies (tid = 12*p + q), twiddled
// from the compact 256-entry w256 table (2 KB, L1-resident at any occupancy).
__device__ __forceinline__ void stage16_mid(const float2 *src, float2 *dst, int tid){
    if (tid < 192){
        float2 v[16];
        int q = tid % 12, p = tid / 12;
        #pragma unroll
        for (int i = 0; i < 16; i++) v[i] = src[PHY(tid + 192*i)];
        dft16(v);
        #pragma unroll
        for (int k = 0; k < 16; k++){
            float2 X = v[(k>>2) + 4*(k&3)];
            if (k && p) X = cmul(X, g_twt.tw2[(p<<4) + k]);   // w256^{pk}
            dst[PHY(q + 192*p + 12*k)] = X;
        }
    }
    __syncthreads();
}

// radix-16 LAST stage: src -> dst, NO twiddle, output mapping tid + 192*k
__device__ __forceinline__ void stage16_last(const float2 *src, float2 *dst, int tid){
    if (tid < 192){
        float2 v[16];
        #pragma unroll
        for (int i = 0; i < 16; i++) v[i] = src[PHY(tid + 192*i)];
        dft16(v);
        #pragma unroll
        for (int k = 0; k < 16; k++){
            float2 X = v[(k>>2) + 4*(k&3)];
            dst[PHY(tid + 192*k)] = X;
        }
    }
    __syncthreads();
}

// ---------------------------------------------------------------- kernels
// One block = one PAIR of frames (2u, 2u+1) packed as z = x + i*y.
// Fully fused: gmem->stage1, filter->stage1', stage3'->merged-OLA-pair->gmem.
// Stage-1 twiddles chained from tw1[p] (w3072^p); tables total 4 KB so L1
// stays effective even at 4 blocks/SM (202 KB smem leaves ~26 KB L1).
__global__ void __launch_bounds__(NTHREADS, 4)
synth_kernel(const float* __restrict__ fb, const float* __restrict__ noise){
    extern __shared__ float2 smem2[];
    float2* Za = smem2;          // buffer A
    float2* Zb = smem2 + SBUF;   // buffer B
    __shared__ float gsx[NF];
    __shared__ float gsy[NF];

    int tp  = blockIdx.x;          // pair index u: 0..499
    int b   = blockIdx.y;
    int tid = threadIdx.x;
    int t0  = 2*tp;

    // filter gains for frames t0, t0+1 (consumed after >=3 barriers: safe)
    if (tid < NF){
        float2 g2 = *(const float2*)&fb[(b*NF + tid)*NT + t0];
        gsx[tid] = g2.x;
        gsy[tid] = g2.y;
    }

    int base = t0*HOP - HALF;
    const float* nb = noise + b*NOISE_LEN;

    // ======== forward FFT: gmem -> s1 -> Zb -> s2(mid) -> Za -> s3(last) -> Zb
    {
        float2 v[12];
        int p = tid;
        #pragma unroll
        for (int i = 0; i < 12; i++){
            int n  = p + 256*i;
            int i0 = base + n;
            int i1 = i0 + HOP;
            float x = (i0 >= 0 && i0 < NOISE_LEN) ? __ldg(&nb[i0]) : 0.0f;
            float y = (i1 >= 0 && i1 < NOISE_LEN) ? __ldg(&nb[i1]) : 0.0f;
            v[i] = make_float2(x, y);
        }
        float2 w1 = g_twt.tw1[p];                // w3072^p (coalesced, 2 KB table)
        dft12(v);
        Zb[PHY(12*p)] = v[0];
        float2 wc = w1;                          // wc = w3072^{p*k}
        #pragma unroll
        for (int k = 1; k < 12; k++){
            Zb[PHY(12*p + k)] = cmul(v[(k/3) + 4*(k%3)], wc);
            if (k < 11) wc = cmul(wc, w1);
        }
        __syncthreads();
    }
    stage16_mid (Zb, Za, tid);   // s2 (twiddled)
    stage16_last(Za, Zb, tid);   // s3 (no twiddle): forward spectrum now in Zb

    // ======== inverse FFT with fused filter:
    //   s1' reads filtered spectrum directly from Zb, writes Za
    {
        float2 v[12];
        int p = tid;
        #pragma unroll
        for (int i = 0; i < 12; i++){
            int n = p + 256*i;
            float2 W;
            if (n == 0){
                W = make_float2(0.0f, 0.0f);                 // H[0] = 0
            } else if (n == HALF){
                float2 A = Zb[PHY(HALF)];                    // Nyquist (X,Y real)
                W = make_float2(gsx[NF-1]*A.x, -gsy[NF-1]*A.y);
            } else {
                int k    = (n < HALF) ? n : (WIN - n);       // 1..1535
                float2 A = Zb[PHY(k)];
                float2 B = Zb[PHY(WIN - k)];
                float Xx = 0.5f*(A.x + B.x), Xy = 0.5f*(A.y - B.y);
                float Yx = 0.5f*(A.y + B.y), Yy = -0.5f*(A.x - B.x);
                int band = (k - 1)/12;
                float hx = gsx[band], hy = gsy[band];
                if (n < HALF){
                    W = make_float2(hx*Xx - hy*Yy, -(hx*Xy + hy*Yx));
                } else {
                    W = make_float2(hx*Xx + hy*Yy, -(-hx*Xy + hy*Yx));
                }
            }
            v[i] = W;
        }
        float2 w1 = g_twt.tw1[p];
        dft12(v);
        Za[PHY(12*p)] = v[0];
        float2 wc = w1;
        #pragma unroll
        for (int k = 1; k < 12; k++){
            Za[PHY(12*p + k)] = cmul(v[(k/3) + 4*(k%3)], wc);
            if (k < 11) wc = cmul(wc, w1);
        }
        __syncthreads();
    }
    stage16_mid(Za, Zb, tid);   // s2' (twiddled)

    // s3' (last, no twiddle): Zb -> registers -> merged pair-OLA -> fp16 gmem.
    //   P[m] = w[m]*f0[m] + w[m-192]*f1[m-192], m in [0,3264); register-local.
    if (tid < 192){
        float2 v[16];
        #pragma unroll
        for (int i = 0; i < 16; i++) v[i] = Zb[PHY(tid + 192*i)];
        dft16(v);
        const float inv = 1.0f/(float)WIN;
        __half* sc = g_scratch + (size_t)(b*NPAIR + tp)*PLEN;
        float prev = 0.0f;   // f1[n(j-1)] * w[n(j-1)]
        #pragma unroll
        for (int j = 0; j < 16; j++){
            float2 X = v[(j>>2) + 4*(j&3)];
            float wj = inv * __ldg(&g_hant.h[tid + 192*j]);
            sc[tid + 192*j] = __float2half_rn(X.x*wj + prev);
            prev = -X.y*wj;
        }
        sc[tid + 192*16] = __float2half_rn(prev);   // m in [3072, 3264): f1 only
    }
}

// 8 consecutive outputs per thread. Pair-frames span 3264 with stride 384.
// s % 8 == 0 and o = s - 384u is a multiple of 8 with o <= 3256, so every
// u in [u_lo, u_hi] is valid for all 8 elements: edge-free 16-byte loads.
__global__ void ola_kernel(float* __restrict__ out){
    const int GP = NOISE_LEN/8;            // 23976 groups per batch
    int gid = blockIdx.x*blockDim.x + threadIdx.x;
    if (gid >= NB*GP) return;
    int b = gid / GP;
    int g = gid - b*GP;
    int s = 8*g + HALF;                    // padded-timeline position, s % 8 == 0
    const __half* base = g_scratch + (size_t)b*NPAIR*PLEN;

    int u_hi = s/384;                  if (u_hi > NPAIR-1) u_hi = NPAIR-1;
    int u_lo = (s >= PLEN) ? (s - PLEN)/384 + 1 : 0;

    float acc[8] = {0.f,0.f,0.f,0.f,0.f,0.f,0.f,0.f};
    for (int u = u_lo; u <= u_hi; u++){
        const uint4 raw = *(const uint4*)&base[(size_t)u*PLEN + (s - 384*u)];
        const __half2* h2 = (const __half2*)&raw;
        #pragma unroll
        for (int j = 0; j < 4; j++){
            float2 f = __half22float2(h2[j]);
            acc[2*j]   += f.x;
            acc[2*j+1] += f.y;
        }
    }
    float4* po = (float4*)&out[b*NOISE_LEN + 8*g];
    po[0] = make_float4(acc[0], acc[1], acc[2], acc[3]);
    po[1] = make_float4(acc[4], acc[5], acc[6], acc[7]);
}

// ---------------------------------------------------------------- launch
extern "C" void kernel_launch(void* const* d_in, const int* in_sizes, int n_in,
                              void* d_out, int out_size){
    const float* fb    = (const float*)d_in[0];
    const float* noise = (const float*)d_in[1];
    if (n_in >= 2 && in_sizes[0] == NB*NOISE_LEN && in_sizes[1] == NB*NF*NT){
        const float* tmp = fb; fb = noise; noise = tmp;
    }
    float* out = (float*)d_out;

    cudaFuncSetAttribute(synth_kernel,
                         cudaFuncAttributeMaxDynamicSharedMemorySize, SMEM_BYTES);

    dim3 grid(NPAIR, NB);
    synth_kernel<<<grid, NTHREADS, SMEM_BYTES>>>(fb, noise);
    int n_groups = NB*(NOISE_LEN/8);
    ola_kernel<<<(n_groups + 255)/256, 256>>>(out);
}